// round 1
// baseline (speedup 1.0000x reference)
#include <cuda_runtime.h>
#include <cstdint>
#include <cstddef>

// Problem dims (fixed by the reference)
#define Bd   2
#define Sd   2048
#define Hd   4096
#define NHd  32
#define HDd  128
#define Md   (Bd * Sd)        // 4096 rows of hidden
#define QKVN (3 * Hd)         // 12288

#define NEG_INF __int_as_float(0xff800000)

// Scratch (allocation-free rule: __device__ globals)
static __device__ float g_qkv[(size_t)Md * QKVN];   // [M, 3H]  (~201 MB)
static __device__ float g_ctx[(size_t)Md * Hd];     // [M, H]   (~67 MB)
static __device__ float g_cos[Md * 64];             // per (b,s,d-pair) rotary cos
static __device__ float g_sin[Md * 64];

// ---------------------------------------------------------------------------
// RoPE trig table in double precision (matches fp32 reference to ~1e-7)
// ---------------------------------------------------------------------------
__global__ void build_trig(const int* __restrict__ pos) {
    int i = blockIdx.x * blockDim.x + threadIdx.x;
    if (i >= Md * 64) return;
    int d = i & 63;
    int m = i >> 6;
    // inv_freq = 10000^(-d/64) = exp(-d * ln(10000)/64)
    double a = (double)pos[m] * exp(-(double)d * 0.1439115683121279);
    g_cos[i] = (float)cos(a);
    g_sin[i] = (float)sin(a);
}

// ---------------------------------------------------------------------------
// Apply NeoX RoPE in-place to Q and K halves of g_qkv
// ---------------------------------------------------------------------------
__global__ void rope_kernel() {
    int i = blockIdx.x * blockDim.x + threadIdx.x;
    if (i >= Md * NHd * 64) return;
    int d = i & 63;
    int h = (i >> 6) & (NHd - 1);
    int m = i >> 11;
    float c  = g_cos[(m << 6) + d];
    float sn = g_sin[(m << 6) + d];
    size_t base = (size_t)m * QKVN + (size_t)h * HDd;
    float* q = g_qkv + base;
    float* k = q + Hd;
    float q1 = q[d], q2 = q[d + 64];
    q[d]      = q1 * c - q2 * sn;
    q[d + 64] = q2 * c + q1 * sn;
    float k1 = k[d], k2 = k[d + 64];
    k[d]      = k1 * c - k2 * sn;
    k[d + 64] = k2 * c + k1 * sn;
}

// ---------------------------------------------------------------------------
// C[M,N] = A[M,K] @ B[N,K]^T + bias[N]   (both row-major, K contiguous)
// 128x128x16 tiles, double-buffered smem, 256 threads, 8x8 per thread.
// M, N assumed multiples of 128; K multiple of 16 (true for all our shapes).
// ---------------------------------------------------------------------------
__global__ __launch_bounds__(256) void gemm_nt_bias(
    const float* __restrict__ A, const float* __restrict__ Bm,
    const float* __restrict__ bias, float* __restrict__ C,
    int Ndim, int Kdim)
{
    __shared__ float As[2][16][128];
    __shared__ float Bs[2][16][128];
    const int tid = threadIdx.x;
    const int tx = tid & 15, ty = tid >> 4;
    const size_t row0 = (size_t)blockIdx.y * 128;
    const size_t col0 = (size_t)blockIdx.x * 128;
    const float* Ag = A + row0 * Kdim;
    const float* Bg = Bm + col0 * Kdim;

    float acc[8][8];
#pragma unroll
    for (int i = 0; i < 8; i++)
#pragma unroll
        for (int j = 0; j < 8; j++) acc[i][j] = 0.f;

    // Each thread loads 2 float4 of A and 2 of B per k-stage.
    const int r0 = tid >> 2;            // 0..63
    const int r1 = r0 + 64;             // 64..127
    const int kk4 = (tid & 3) << 2;     // 0,4,8,12

    // initial stage 0 load
    {
        float4 a0 = *(const float4*)(Ag + (size_t)r0 * Kdim + kk4);
        float4 a1 = *(const float4*)(Ag + (size_t)r1 * Kdim + kk4);
        float4 b0 = *(const float4*)(Bg + (size_t)r0 * Kdim + kk4);
        float4 b1 = *(const float4*)(Bg + (size_t)r1 * Kdim + kk4);
        As[0][kk4+0][r0]=a0.x; As[0][kk4+1][r0]=a0.y; As[0][kk4+2][r0]=a0.z; As[0][kk4+3][r0]=a0.w;
        As[0][kk4+0][r1]=a1.x; As[0][kk4+1][r1]=a1.y; As[0][kk4+2][r1]=a1.z; As[0][kk4+3][r1]=a1.w;
        Bs[0][kk4+0][r0]=b0.x; Bs[0][kk4+1][r0]=b0.y; Bs[0][kk4+2][r0]=b0.z; Bs[0][kk4+3][r0]=b0.w;
        Bs[0][kk4+0][r1]=b1.x; Bs[0][kk4+1][r1]=b1.y; Bs[0][kk4+2][r1]=b1.z; Bs[0][kk4+3][r1]=b1.w;
    }
    __syncthreads();

    int buf = 0;
    for (int k0 = 0; k0 < Kdim; k0 += 16) {
        float4 pa0, pa1, pb0, pb1;
        const bool nxt = (k0 + 16) < Kdim;
        if (nxt) {
            const float* Agn = Ag + k0 + 16;
            const float* Bgn = Bg + k0 + 16;
            pa0 = *(const float4*)(Agn + (size_t)r0 * Kdim + kk4);
            pa1 = *(const float4*)(Agn + (size_t)r1 * Kdim + kk4);
            pb0 = *(const float4*)(Bgn + (size_t)r0 * Kdim + kk4);
            pb1 = *(const float4*)(Bgn + (size_t)r1 * Kdim + kk4);
        }
#pragma unroll
        for (int kk = 0; kk < 16; ++kk) {
            float4 a0 = *(const float4*)&As[buf][kk][ty * 8];
            float4 a1 = *(const float4*)&As[buf][kk][ty * 8 + 4];
            float4 b0 = *(const float4*)&Bs[buf][kk][tx * 8];
            float4 b1 = *(const float4*)&Bs[buf][kk][tx * 8 + 4];
            float av[8] = {a0.x,a0.y,a0.z,a0.w,a1.x,a1.y,a1.z,a1.w};
            float bv[8] = {b0.x,b0.y,b0.z,b0.w,b1.x,b1.y,b1.z,b1.w};
#pragma unroll
            for (int i = 0; i < 8; i++)
#pragma unroll
                for (int j = 0; j < 8; j++)
                    acc[i][j] = fmaf(av[i], bv[j], acc[i][j]);
        }
        if (nxt) {
            int nb = buf ^ 1;
            As[nb][kk4+0][r0]=pa0.x; As[nb][kk4+1][r0]=pa0.y; As[nb][kk4+2][r0]=pa0.z; As[nb][kk4+3][r0]=pa0.w;
            As[nb][kk4+0][r1]=pa1.x; As[nb][kk4+1][r1]=pa1.y; As[nb][kk4+2][r1]=pa1.z; As[nb][kk4+3][r1]=pa1.w;
            Bs[nb][kk4+0][r0]=pb0.x; Bs[nb][kk4+1][r0]=pb0.y; Bs[nb][kk4+2][r0]=pb0.z; Bs[nb][kk4+3][r0]=pb0.w;
            Bs[nb][kk4+0][r1]=pb1.x; Bs[nb][kk4+1][r1]=pb1.y; Bs[nb][kk4+2][r1]=pb1.z; Bs[nb][kk4+3][r1]=pb1.w;
            __syncthreads();
            buf = nb;
        }
    }

    float bv[8];
#pragma unroll
    for (int j = 0; j < 8; j++) bv[j] = bias[col0 + tx * 8 + j];
#pragma unroll
    for (int i = 0; i < 8; i++) {
        float* cp = C + (row0 + ty * 8 + i) * (size_t)Ndim + col0 + tx * 8;
        *(float4*)cp       = make_float4(acc[i][0]+bv[0], acc[i][1]+bv[1], acc[i][2]+bv[2], acc[i][3]+bv[3]);
        *(float4*)(cp + 4) = make_float4(acc[i][4]+bv[4], acc[i][5]+bv[5], acc[i][6]+bv[6], acc[i][7]+bv[7]);
    }
}

// ---------------------------------------------------------------------------
// Causal flash attention, fp32. Block = (q-tile of 64) x (b,h). 256 threads.
// Thread (tx,ty) owns query rows ty*4..+3; score cols c = tx + 16*j (j<4);
// output cols tx*8..+7. Online softmax, P staged via smem for PV.
// ---------------------------------------------------------------------------
#define APAD 132   // row stride for Q/K/V smem tiles (pad vs 128)

__global__ __launch_bounds__(256) void attn_kernel() {
    extern __shared__ float sm[];
    float* Qs = sm;                 // [64][APAD]
    float* Ks = Qs + 64 * APAD;     // [64][APAD]
    float* Vs = Ks + 64 * APAD;     // [64][APAD]
    float* Ps = Vs + 64 * APAD;     // [64][64]

    const int tid = threadIdx.x;
    const int tx = tid & 15, ty = tid >> 4;
    const int q0 = blockIdx.x << 6;
    const int bh = blockIdx.y;
    const int b  = bh >> 5, h = bh & 31;

    const float* qbase = g_qkv + (size_t)b * Sd * QKVN + (size_t)h * HDd;
    const float* kbase = qbase + Hd;
    const float* vbase = qbase + 2 * Hd;
    const float scale = 0.08838834764831845f;   // 1/sqrt(128)

    // Load Q tile, scale folded in. 2048 float4, coalesced.
#pragma unroll
    for (int t = 0; t < 8; t++) {
        int idx = t * 256 + tid;
        int r = idx >> 5, d4 = (idx & 31) << 2;
        float4 v = *(const float4*)(qbase + (size_t)(q0 + r) * QKVN + d4);
        *(float4*)&Qs[r * APAD + d4] = make_float4(v.x*scale, v.y*scale, v.z*scale, v.w*scale);
    }

    float m_i[4], l_i[4], acc[4][8];
#pragma unroll
    for (int i = 0; i < 4; i++) {
        m_i[i] = NEG_INF; l_i[i] = 0.f;
#pragma unroll
        for (int c = 0; c < 8; c++) acc[i][c] = 0.f;
    }

    for (int j0 = 0; j0 <= q0; j0 += 64) {
        __syncthreads();   // previous PV done (and Q tile visible on first iter)
#pragma unroll
        for (int t = 0; t < 8; t++) {
            int idx = t * 256 + tid;
            int r = idx >> 5, d4 = (idx & 31) << 2;
            *(float4*)&Ks[r * APAD + d4] = *(const float4*)(kbase + (size_t)(j0 + r) * QKVN + d4);
            *(float4*)&Vs[r * APAD + d4] = *(const float4*)(vbase + (size_t)(j0 + r) * QKVN + d4);
        }
        __syncthreads();

        // S = Q K^T (scale pre-folded). s[i][j]: row ty*4+i, key col tx+16j.
        float s[4][4];
#pragma unroll
        for (int i = 0; i < 4; i++)
#pragma unroll
            for (int j = 0; j < 4; j++) s[i][j] = 0.f;

#pragma unroll 4
        for (int d4 = 0; d4 < 128; d4 += 4) {
            float4 q[4], k[4];
#pragma unroll
            for (int i = 0; i < 4; i++) q[i] = *(const float4*)&Qs[(ty*4 + i) * APAD + d4];
#pragma unroll
            for (int j = 0; j < 4; j++) k[j] = *(const float4*)&Ks[(tx + 16*j) * APAD + d4];
#pragma unroll
            for (int i = 0; i < 4; i++)
#pragma unroll
                for (int j = 0; j < 4; j++) {
                    s[i][j] = fmaf(q[i].x, k[j].x, s[i][j]);
                    s[i][j] = fmaf(q[i].y, k[j].y, s[i][j]);
                    s[i][j] = fmaf(q[i].z, k[j].z, s[i][j]);
                    s[i][j] = fmaf(q[i].w, k[j].w, s[i][j]);
                }
        }

        if (j0 == q0) {   // diagonal tile: causal mask
#pragma unroll
            for (int i = 0; i < 4; i++)
#pragma unroll
                for (int j = 0; j < 4; j++)
                    if (tx + 16*j > ty*4 + i) s[i][j] = NEG_INF;
        }

        // Online softmax update per row
#pragma unroll
        for (int i = 0; i < 4; i++) {
            float mx = fmaxf(fmaxf(s[i][0], s[i][1]), fmaxf(s[i][2], s[i][3]));
#pragma unroll
            for (int o = 8; o; o >>= 1) mx = fmaxf(mx, __shfl_xor_sync(0xffffffffu, mx, o));
            float mn = fmaxf(m_i[i], mx);
            float al = __expf(m_i[i] - mn);
            m_i[i] = mn;
            float ssum = 0.f;
#pragma unroll
            for (int j = 0; j < 4; j++) {
                float p = __expf(s[i][j] - mn);
                Ps[(ty*4 + i) * 64 + tx + 16*j] = p;
                ssum += p;
            }
#pragma unroll
            for (int o = 8; o; o >>= 1) ssum += __shfl_xor_sync(0xffffffffu, ssum, o);
            l_i[i] = l_i[i] * al + ssum;
#pragma unroll
            for (int c = 0; c < 8; c++) acc[i][c] *= al;
        }
        __syncthreads();

        // acc += P @ V   (output cols tx*8..+7)
#pragma unroll 2
        for (int j = 0; j < 64; j += 4) {
            float4 p[4];
#pragma unroll
            for (int i = 0; i < 4; i++) p[i] = *(const float4*)&Ps[(ty*4 + i) * 64 + j];
#pragma unroll
            for (int jj = 0; jj < 4; jj++) {
                float4 v0 = *(const float4*)&Vs[(j + jj) * APAD + tx*8];
                float4 v1 = *(const float4*)&Vs[(j + jj) * APAD + tx*8 + 4];
#pragma unroll
                for (int i = 0; i < 4; i++) {
                    float pv = (jj == 0) ? p[i].x : (jj == 1) ? p[i].y : (jj == 2) ? p[i].z : p[i].w;
                    acc[i][0] = fmaf(pv, v0.x, acc[i][0]);
                    acc[i][1] = fmaf(pv, v0.y, acc[i][1]);
                    acc[i][2] = fmaf(pv, v0.z, acc[i][2]);
                    acc[i][3] = fmaf(pv, v0.w, acc[i][3]);
                    acc[i][4] = fmaf(pv, v1.x, acc[i][4]);
                    acc[i][5] = fmaf(pv, v1.y, acc[i][5]);
                    acc[i][6] = fmaf(pv, v1.z, acc[i][6]);
                    acc[i][7] = fmaf(pv, v1.w, acc[i][7]);
                }
            }
        }
    }

    // Normalize and write ctx[b, s, h*HD + c]
#pragma unroll
    for (int i = 0; i < 4; i++) {
        float inv = 1.f / l_i[i];
        float* o = g_ctx + (size_t)(b * Sd + q0 + ty*4 + i) * Hd + h * HDd + tx * 8;
        *(float4*)o       = make_float4(acc[i][0]*inv, acc[i][1]*inv, acc[i][2]*inv, acc[i][3]*inv);
        *(float4*)(o + 4) = make_float4(acc[i][4]*inv, acc[i][5]*inv, acc[i][6]*inv, acc[i][7]*inv);
    }
}

// ---------------------------------------------------------------------------
// Launch
// ---------------------------------------------------------------------------
extern "C" void kernel_launch(void* const* d_in, const int* in_sizes, int n_in,
                              void* d_out, int out_size)
{
    const int*   pos   = (const int*)  d_in[0];
    const float* hid   = (const float*)d_in[1];
    const float* w_qkv = (const float*)d_in[2];
    const float* b_qkv = (const float*)d_in[3];
    const float* w_out = (const float*)d_in[4];
    const float* b_out = (const float*)d_in[5];
    float* out = (float*)d_out;

    (void)in_sizes; (void)n_in; (void)out_size;

    const size_t attn_smem = (size_t)(3 * 64 * APAD + 64 * 64) * sizeof(float); // 117760 B
    cudaFuncSetAttribute(attn_kernel, cudaFuncAttributeMaxDynamicSharedMemorySize, (int)attn_smem);

    float* qkv_ptr = nullptr;
    float* ctx_ptr = nullptr;
    cudaGetSymbolAddress((void**)&qkv_ptr, g_qkv);
    cudaGetSymbolAddress((void**)&ctx_ptr, g_ctx);

    build_trig<<<(Md * 64 + 255) / 256, 256>>>(pos);
    gemm_nt_bias<<<dim3(QKVN / 128, Md / 128), 256>>>(hid, w_qkv, b_qkv, qkv_ptr, QKVN, Hd);
    rope_kernel<<<(Md * NHd * 64 + 255) / 256, 256>>>();
    attn_kernel<<<dim3(Sd / 64, Bd * NHd), 256, attn_smem>>>();
    gemm_nt_bias<<<dim3(Hd / 128, Md / 128), 256>>>(ctx_ptr, w_out, b_out, out, Hd, Hd);
}

// round 3
// speedup vs baseline: 2.3413x; 2.3413x over previous
#include <cuda_runtime.h>
#include <cuda_bf16.h>
#include <cstdint>
#include <cstddef>

// Problem dims (fixed)
#define Bd   2
#define Sd   2048
#define Hd   4096
#define NHd  32
#define HDd  128
#define Md   (Bd * Sd)        // 4096
#define QKVN (3 * Hd)         // 12288
#define Kdim 4096             // K of both GEMMs

#define NEG_INF __int_as_float(0xff800000)

// ---------------------------------------------------------------------------
// Scratch (__device__ globals; allocation-free rule)
// ---------------------------------------------------------------------------
static __device__ float g_qkv[(size_t)Md * QKVN];
static __device__ float g_ctx[(size_t)Md * Hd];
static __device__ float g_cos[Md * 64];
static __device__ float g_sin[Md * 64];
static __device__ __nv_bfloat16 g_hid_hi[(size_t)Md * Hd];
static __device__ __nv_bfloat16 g_hid_lo[(size_t)Md * Hd];
static __device__ __nv_bfloat16 g_wqkv_hi[(size_t)QKVN * Hd];
static __device__ __nv_bfloat16 g_wqkv_lo[(size_t)QKVN * Hd];
static __device__ __nv_bfloat16 g_wout_hi[(size_t)Hd * Hd];
static __device__ __nv_bfloat16 g_wout_lo[(size_t)Hd * Hd];
static __device__ __nv_bfloat16 g_ctx_hi[(size_t)Md * Hd];
static __device__ __nv_bfloat16 g_ctx_lo[(size_t)Md * Hd];

// ---------------------------------------------------------------------------
// Helpers
// ---------------------------------------------------------------------------
__device__ __forceinline__ uint32_t smem_to_u32(const void* p) {
    uint32_t a;
    asm("{ .reg .u64 t; cvta.to.shared.u64 t, %1; cvt.u32.u64 %0, t; }" : "=r"(a) : "l"(p));
    return a;
}

#define LDSM4(r, addr) \
    asm volatile("ldmatrix.sync.aligned.m8n8.x4.shared.b16 {%0,%1,%2,%3}, [%4];" \
        : "=r"((r)[0]), "=r"((r)[1]), "=r"((r)[2]), "=r"((r)[3]) : "r"(addr))

#define MMA16816(c, a, b) \
    asm volatile("mma.sync.aligned.m16n8k16.row.col.f32.bf16.bf16.f32 " \
        "{%0,%1,%2,%3}, {%4,%5,%6,%7}, {%8,%9}, {%0,%1,%2,%3};" \
        : "+f"((c)[0]), "+f"((c)[1]), "+f"((c)[2]), "+f"((c)[3]) \
        : "r"((a)[0]), "r"((a)[1]), "r"((a)[2]), "r"((a)[3]), "r"((b)[0]), "r"((b)[1]))

// ---------------------------------------------------------------------------
// RoPE trig table in double precision
// ---------------------------------------------------------------------------
__global__ void build_trig(const int* __restrict__ pos) {
    int i = blockIdx.x * blockDim.x + threadIdx.x;
    if (i >= Md * 64) return;
    int d = i & 63;
    int m = i >> 6;
    double a = (double)pos[m] * exp(-(double)d * 0.1439115683121279);
    g_cos[i] = (float)cos(a);
    g_sin[i] = (float)sin(a);
}

// ---------------------------------------------------------------------------
// fp32 -> bf16 hi/lo split
// ---------------------------------------------------------------------------
__global__ void split_kernel(const float* __restrict__ src,
                             __nv_bfloat16* __restrict__ hi,
                             __nv_bfloat16* __restrict__ lo, int n4) {
    int i = blockIdx.x * blockDim.x + threadIdx.x;
    if (i >= n4) return;
    float4 v = ((const float4*)src)[i];
    __nv_bfloat16 h0 = __float2bfloat16(v.x);
    __nv_bfloat16 h1 = __float2bfloat16(v.y);
    __nv_bfloat16 h2 = __float2bfloat16(v.z);
    __nv_bfloat16 h3 = __float2bfloat16(v.w);
    __nv_bfloat16 l0 = __float2bfloat16(v.x - __bfloat162float(h0));
    __nv_bfloat16 l1 = __float2bfloat16(v.y - __bfloat162float(h1));
    __nv_bfloat16 l2 = __float2bfloat16(v.z - __bfloat162float(h2));
    __nv_bfloat16 l3 = __float2bfloat16(v.w - __bfloat162float(h3));
    ((__nv_bfloat162*)hi)[i * 2]     = __nv_bfloat162(h0, h1);
    ((__nv_bfloat162*)hi)[i * 2 + 1] = __nv_bfloat162(h2, h3);
    ((__nv_bfloat162*)lo)[i * 2]     = __nv_bfloat162(l0, l1);
    ((__nv_bfloat162*)lo)[i * 2 + 1] = __nv_bfloat162(l2, l3);
}

// ---------------------------------------------------------------------------
// NeoX RoPE in-place on Q,K halves of g_qkv
// ---------------------------------------------------------------------------
__global__ void rope_kernel() {
    int i = blockIdx.x * blockDim.x + threadIdx.x;
    if (i >= Md * NHd * 64) return;
    int d = i & 63;
    int h = (i >> 6) & (NHd - 1);
    int m = i >> 11;
    float c  = g_cos[(m << 6) + d];
    float sn = g_sin[(m << 6) + d];
    size_t base = (size_t)m * QKVN + (size_t)h * HDd;
    float* q = g_qkv + base;
    float* k = q + Hd;
    float q1 = q[d], q2 = q[d + 64];
    q[d]      = q1 * c - q2 * sn;
    q[d + 64] = q2 * c + q1 * sn;
    float k1 = k[d], k2 = k[d + 64];
    k[d]      = k1 * c - k2 * sn;
    k[d + 64] = k2 * c + k1 * sn;
}

// ---------------------------------------------------------------------------
// bf16x3 GEMM on mma.sync: C[M,N] = (Ahi+Alo)@(Bhi+Blo)^T + bias
// CTA 128x128, BK=32, cp.async double buffer, 8 warps (2m x 4n), warp 64x32.
// Smem rows: 64B of k + 16B pad (stride 80) -> conflict-free ldmatrix.
// ---------------------------------------------------------------------------
#define BKg      32
#define TSTRIDE  80
#define TILE_B   (128 * TSTRIDE)     // 10240
#define STAGE_B  (4 * TILE_B)        // 40960

__device__ __forceinline__ void load_stage(uint32_t sbase, const char* const* tp,
                                           int k0, int tid) {
    // 2048 chunks of 16B: tile = idx>>9, r = (idx>>2)&127, c = idx&3
#pragma unroll
    for (int t = 0; t < 8; t++) {
        int idx = t * 256 + tid;
        int tile = idx >> 9;
        int r = (idx >> 2) & 127;
        int c = idx & 3;
        uint32_t saddr = sbase + tile * TILE_B + r * TSTRIDE + c * 16;
        const char* g = tp[tile] + ((size_t)r * Kdim + k0) * 2 + c * 16;
        asm volatile("cp.async.cg.shared.global [%0], [%1], 16;" :: "r"(saddr), "l"(g));
    }
    asm volatile("cp.async.commit_group;" ::: "memory");
}

__global__ __launch_bounds__(256, 2) void gemm_tc(
    const __nv_bfloat16* __restrict__ Ahi, const __nv_bfloat16* __restrict__ Alo,
    const __nv_bfloat16* __restrict__ Bhi, const __nv_bfloat16* __restrict__ Blo,
    const float* __restrict__ bias, float* __restrict__ C,
    int Ndim, int n_coltiles)
{
    extern __shared__ __align__(128) char smem[];
    const uint32_t sb = smem_to_u32(smem);
    const int tid = threadIdx.x;
    const int lane = tid & 31, warp = tid >> 5;
    const int wm = warp & 1, wn = warp >> 1;

    // Band rasterization (8 row-tiles per band) for L2 reuse
    int bid = blockIdx.x;
    int tpb = 8 * n_coltiles;
    int band = bid / tpb;
    int rem = bid - band * tpb;
    size_t row0 = (size_t)(band * 8 + (rem & 7)) * 128;
    size_t col0 = (size_t)(rem >> 3) * 128;

    const char* tp[4] = {
        (const char*)(Ahi + row0 * Kdim),
        (const char*)(Alo + row0 * Kdim),
        (const char*)(Bhi + col0 * Kdim),
        (const char*)(Blo + col0 * Kdim) };

    float acc[4][4][4];
#pragma unroll
    for (int mf = 0; mf < 4; mf++)
#pragma unroll
        for (int nf = 0; nf < 4; nf++)
#pragma unroll
            for (int e = 0; e < 4; e++) acc[mf][nf][e] = 0.f;

    load_stage(sb, tp, 0, tid);

    const int NKB = Kdim / BKg;   // 128
    for (int kb = 0; kb < NKB; kb++) {
        asm volatile("cp.async.wait_group 0;" ::: "memory");
        __syncthreads();
        if (kb + 1 < NKB)
            load_stage(sb + ((kb + 1) & 1) * STAGE_B, tp, (kb + 1) * BKg, tid);
        const uint32_t cs = sb + (kb & 1) * STAGE_B;

#pragma unroll
        for (int ks = 0; ks < 2; ks++) {
            // A fragment base: rows (lane&15), +16B for k-cols 8-15
            const uint32_t a_off = cs + (wm * 64 + (lane & 15)) * TSTRIDE
                                 + ((lane >> 4) * 16) + ks * 32;
            // B fragment base: n rows (lane&7 | hi-8-group), k8-sel via lane bit 3
            const uint32_t b_off = cs + 2 * TILE_B
                                 + (wn * 32 + (lane & 7) + (lane >> 4) * 8) * TSTRIDE
                                 + (((lane >> 3) & 1) * 16) + ks * 32;

            uint32_t ah[4][4], bh[4][2], bt[4][2];
#pragma unroll
            for (int mf = 0; mf < 4; mf++) LDSM4(ah[mf], a_off + mf * 16 * TSTRIDE);
#pragma unroll
            for (int ng = 0; ng < 2; ng++) {
                uint32_t r[4];
                LDSM4(r, b_off + ng * 16 * TSTRIDE);
                bh[ng * 2][0] = r[0]; bh[ng * 2][1] = r[1];
                bh[ng * 2 + 1][0] = r[2]; bh[ng * 2 + 1][1] = r[3];
            }
            // hi * hi
#pragma unroll
            for (int mf = 0; mf < 4; mf++)
#pragma unroll
                for (int nf = 0; nf < 4; nf++) MMA16816(acc[mf][nf], ah[mf], bh[nf]);

            // hi * lo  (B_lo at +TILE_B from B_hi)
#pragma unroll
            for (int ng = 0; ng < 2; ng++) {
                uint32_t r[4];
                LDSM4(r, b_off + TILE_B + ng * 16 * TSTRIDE);
                bt[ng * 2][0] = r[0]; bt[ng * 2][1] = r[1];
                bt[ng * 2 + 1][0] = r[2]; bt[ng * 2 + 1][1] = r[3];
            }
#pragma unroll
            for (int mf = 0; mf < 4; mf++)
#pragma unroll
                for (int nf = 0; nf < 4; nf++) MMA16816(acc[mf][nf], ah[mf], bt[nf]);

            // lo * hi  (A_lo at +TILE_B from A_hi; reuse ah regs)
#pragma unroll
            for (int mf = 0; mf < 4; mf++) LDSM4(ah[mf], a_off + TILE_B + mf * 16 * TSTRIDE);
#pragma unroll
            for (int mf = 0; mf < 4; mf++)
#pragma unroll
                for (int nf = 0; nf < 4; nf++) MMA16816(acc[mf][nf], ah[mf], bh[nf]);
        }
    }

    // Epilogue: fp32 + bias, direct to gmem
#pragma unroll
    for (int mf = 0; mf < 4; mf++) {
        int row = (int)row0 + wm * 64 + mf * 16 + (lane >> 2);
#pragma unroll
        for (int nf = 0; nf < 4; nf++) {
            int col = (int)col0 + wn * 32 + nf * 8 + (lane & 3) * 2;
            float b0 = bias[col], b1 = bias[col + 1];
            float* p0 = C + (size_t)row * Ndim + col;
            *(float2*)p0 = make_float2(acc[mf][nf][0] + b0, acc[mf][nf][1] + b1);
            float* p1 = p0 + 8 * (size_t)Ndim;
            *(float2*)p1 = make_float2(acc[mf][nf][2] + b0, acc[mf][nf][3] + b1);
        }
    }
}

// ---------------------------------------------------------------------------
// Causal flash attention, fp32 (proven round-1 version)
// ---------------------------------------------------------------------------
#define APAD 132

__global__ __launch_bounds__(256) void attn_kernel() {
    extern __shared__ float sm[];
    float* Qs = sm;
    float* Ks = Qs + 64 * APAD;
    float* Vs = Ks + 64 * APAD;
    float* Ps = Vs + 64 * APAD;

    const int tid = threadIdx.x;
    const int tx = tid & 15, ty = tid >> 4;
    const int q0 = blockIdx.x << 6;
    const int bh = blockIdx.y;
    const int b  = bh >> 5, h = bh & 31;

    const float* qbase = g_qkv + (size_t)b * Sd * QKVN + (size_t)h * HDd;
    const float* kbase = qbase + Hd;
    const float* vbase = qbase + 2 * Hd;
    const float scale = 0.08838834764831845f;

#pragma unroll
    for (int t = 0; t < 8; t++) {
        int idx = t * 256 + tid;
        int r = idx >> 5, d4 = (idx & 31) << 2;
        float4 v = *(const float4*)(qbase + (size_t)(q0 + r) * QKVN + d4);
        *(float4*)&Qs[r * APAD + d4] = make_float4(v.x*scale, v.y*scale, v.z*scale, v.w*scale);
    }

    float m_i[4], l_i[4], acc[4][8];
#pragma unroll
    for (int i = 0; i < 4; i++) {
        m_i[i] = NEG_INF; l_i[i] = 0.f;
#pragma unroll
        for (int c = 0; c < 8; c++) acc[i][c] = 0.f;
    }

    for (int j0 = 0; j0 <= q0; j0 += 64) {
        __syncthreads();
#pragma unroll
        for (int t = 0; t < 8; t++) {
            int idx = t * 256 + tid;
            int r = idx >> 5, d4 = (idx & 31) << 2;
            *(float4*)&Ks[r * APAD + d4] = *(const float4*)(kbase + (size_t)(j0 + r) * QKVN + d4);
            *(float4*)&Vs[r * APAD + d4] = *(const float4*)(vbase + (size_t)(j0 + r) * QKVN + d4);
        }
        __syncthreads();

        float s[4][4];
#pragma unroll
        for (int i = 0; i < 4; i++)
#pragma unroll
            for (int j = 0; j < 4; j++) s[i][j] = 0.f;

#pragma unroll 4
        for (int d4 = 0; d4 < 128; d4 += 4) {
            float4 q[4], k[4];
#pragma unroll
            for (int i = 0; i < 4; i++) q[i] = *(const float4*)&Qs[(ty*4 + i) * APAD + d4];
#pragma unroll
            for (int j = 0; j < 4; j++) k[j] = *(const float4*)&Ks[(tx + 16*j) * APAD + d4];
#pragma unroll
            for (int i = 0; i < 4; i++)
#pragma unroll
                for (int j = 0; j < 4; j++) {
                    s[i][j] = fmaf(q[i].x, k[j].x, s[i][j]);
                    s[i][j] = fmaf(q[i].y, k[j].y, s[i][j]);
                    s[i][j] = fmaf(q[i].z, k[j].z, s[i][j]);
                    s[i][j] = fmaf(q[i].w, k[j].w, s[i][j]);
                }
        }

        if (j0 == q0) {
#pragma unroll
            for (int i = 0; i < 4; i++)
#pragma unroll
                for (int j = 0; j < 4; j++)
                    if (tx + 16*j > ty*4 + i) s[i][j] = NEG_INF;
        }

#pragma unroll
        for (int i = 0; i < 4; i++) {
            float mx = fmaxf(fmaxf(s[i][0], s[i][1]), fmaxf(s[i][2], s[i][3]));
#pragma unroll
            for (int o = 8; o; o >>= 1) mx = fmaxf(mx, __shfl_xor_sync(0xffffffffu, mx, o));
            float mn = fmaxf(m_i[i], mx);
            float al = __expf(m_i[i] - mn);
            m_i[i] = mn;
            float ssum = 0.f;
#pragma unroll
            for (int j = 0; j < 4; j++) {
                float p = __expf(s[i][j] - mn);
                Ps[(ty*4 + i) * 64 + tx + 16*j] = p;
                ssum += p;
            }
#pragma unroll
            for (int o = 8; o; o >>= 1) ssum += __shfl_xor_sync(0xffffffffu, ssum, o);
            l_i[i] = l_i[i] * al + ssum;
#pragma unroll
            for (int c = 0; c < 8; c++) acc[i][c] *= al;
        }
        __syncthreads();

#pragma unroll 2
        for (int j = 0; j < 64; j += 4) {
            float4 p[4];
#pragma unroll
            for (int i = 0; i < 4; i++) p[i] = *(const float4*)&Ps[(ty*4 + i) * 64 + j];
#pragma unroll
            for (int jj = 0; jj < 4; jj++) {
                float4 v0 = *(const float4*)&Vs[(j + jj) * APAD + tx*8];
                float4 v1 = *(const float4*)&Vs[(j + jj) * APAD + tx*8 + 4];
#pragma unroll
                for (int i = 0; i < 4; i++) {
                    float pv = (jj == 0) ? p[i].x : (jj == 1) ? p[i].y : (jj == 2) ? p[i].z : p[i].w;
                    acc[i][0] = fmaf(pv, v0.x, acc[i][0]);
                    acc[i][1] = fmaf(pv, v0.y, acc[i][1]);
                    acc[i][2] = fmaf(pv, v0.z, acc[i][2]);
                    acc[i][3] = fmaf(pv, v0.w, acc[i][3]);
                    acc[i][4] = fmaf(pv, v1.x, acc[i][4]);
                    acc[i][5] = fmaf(pv, v1.y, acc[i][5]);
                    acc[i][6] = fmaf(pv, v1.z, acc[i][6]);
                    acc[i][7] = fmaf(pv, v1.w, acc[i][7]);
                }
            }
        }
    }

#pragma unroll
    for (int i = 0; i < 4; i++) {
        float inv = 1.f / l_i[i];
        float* o = g_ctx + (size_t)(b * Sd + q0 + ty*4 + i) * Hd + h * HDd + tx * 8;
        *(float4*)o       = make_float4(acc[i][0]*inv, acc[i][1]*inv, acc[i][2]*inv, acc[i][3]*inv);
        *(float4*)(o + 4) = make_float4(acc[i][4]*inv, acc[i][5]*inv, acc[i][6]*inv, acc[i][7]*inv);
    }
}

// ---------------------------------------------------------------------------
// Launch
// ---------------------------------------------------------------------------
extern "C" void kernel_launch(void* const* d_in, const int* in_sizes, int n_in,
                              void* d_out, int out_size)
{
    const int*   pos   = (const int*)  d_in[0];
    const float* hid   = (const float*)d_in[1];
    const float* w_qkv = (const float*)d_in[2];
    const float* b_qkv = (const float*)d_in[3];
    const float* w_out = (const float*)d_in[4];
    const float* b_out = (const float*)d_in[5];
    float* out = (float*)d_out;
    (void)in_sizes; (void)n_in; (void)out_size;

    const size_t attn_smem = (size_t)(3 * 64 * APAD + 64 * 64) * sizeof(float);
    cudaFuncSetAttribute(attn_kernel, cudaFuncAttributeMaxDynamicSharedMemorySize, (int)attn_smem);
    const size_t gemm_smem = 2 * STAGE_B;   // 81920
    cudaFuncSetAttribute(gemm_tc, cudaFuncAttributeMaxDynamicSharedMemorySize, (int)gemm_smem);

    float* qkv_ptr = nullptr;  float* ctx_ptr = nullptr;
    __nv_bfloat16 *hid_hi, *hid_lo, *wqkv_hi, *wqkv_lo, *wout_hi, *wout_lo, *ctx_hi, *ctx_lo;
    cudaGetSymbolAddress((void**)&qkv_ptr, g_qkv);
    cudaGetSymbolAddress((void**)&ctx_ptr, g_ctx);
    cudaGetSymbolAddress((void**)&hid_hi,  g_hid_hi);
    cudaGetSymbolAddress((void**)&hid_lo,  g_hid_lo);
    cudaGetSymbolAddress((void**)&wqkv_hi, g_wqkv_hi);
    cudaGetSymbolAddress((void**)&wqkv_lo, g_wqkv_lo);
    cudaGetSymbolAddress((void**)&wout_hi, g_wout_hi);
    cudaGetSymbolAddress((void**)&wout_lo, g_wout_lo);
    cudaGetSymbolAddress((void**)&ctx_hi,  g_ctx_hi);
    cudaGetSymbolAddress((void**)&ctx_lo,  g_ctx_lo);

    build_trig<<<(Md * 64 + 255) / 256, 256>>>(pos);

    int n4_hid  = Md * Hd / 4;
    int n4_wqkv = QKVN * Hd / 4;
    int n4_wout = Hd * Hd / 4;
    split_kernel<<<(n4_hid  + 255) / 256, 256>>>(hid,   hid_hi,  hid_lo,  n4_hid);
    split_kernel<<<(n4_wqkv + 255) / 256, 256>>>(w_qkv, wqkv_hi, wqkv_lo, n4_wqkv);
    split_kernel<<<(n4_wout + 255) / 256, 256>>>(w_out, wout_hi, wout_lo, n4_wout);

    // QKV GEMM: [4096,12288]
    gemm_tc<<<(Md / 128) * (QKVN / 128), 256, gemm_smem>>>(
        hid_hi, hid_lo, wqkv_hi, wqkv_lo, b_qkv, qkv_ptr, QKVN, QKVN / 128);

    rope_kernel<<<(Md * NHd * 64 + 255) / 256, 256>>>();
    attn_kernel<<<dim3(Sd / 64, Bd * NHd), 256, attn_smem>>>();

    split_kernel<<<(n4_hid + 255) / 256, 256>>>(ctx_ptr, ctx_hi, ctx_lo, n4_hid);

    // Out GEMM: [4096,4096]
    gemm_tc<<<(Md / 128) * (Hd / 128), 256, gemm_smem>>>(
        ctx_hi, ctx_lo, wout_hi, wout_lo, b_out, out, Hd, Hd / 128);
}

// round 4
// speedup vs baseline: 3.1698x; 1.3538x over previous
#include <cuda_runtime.h>
#include <cuda_bf16.h>
#include <cstdint>
#include <cstddef>

// Problem dims (fixed)
#define Bd   2
#define Sd   2048
#define Hd   4096
#define NHd  32
#define HDd  128
#define Md   (Bd * Sd)        // 4096
#define QKVN (3 * Hd)         // 12288
#define Kdim 4096

#define NEG_INF __int_as_float(0xff800000)

// ---------------------------------------------------------------------------
// Scratch
// ---------------------------------------------------------------------------
static __device__ float g_qkv[(size_t)Md * QKVN];
static __device__ float g_cos[Md * 64];
static __device__ float g_sin[Md * 64];
static __device__ __nv_bfloat16 g_hid_hi[(size_t)Md * Hd];
static __device__ __nv_bfloat16 g_hid_lo[(size_t)Md * Hd];
static __device__ __nv_bfloat16 g_wqkv_hi[(size_t)QKVN * Hd];
static __device__ __nv_bfloat16 g_wqkv_lo[(size_t)QKVN * Hd];
static __device__ __nv_bfloat16 g_wout_hi[(size_t)Hd * Hd];
static __device__ __nv_bfloat16 g_wout_lo[(size_t)Hd * Hd];
static __device__ __nv_bfloat16 g_ctx_hi[(size_t)Md * Hd];
static __device__ __nv_bfloat16 g_ctx_lo[(size_t)Md * Hd];
// attention operands, [b,h,s,d] (Q,K) and [b,h,d,s] (V^T), bf16 hi/lo
static __device__ __nv_bfloat16 g_qh[(size_t)Md * Hd];
static __device__ __nv_bfloat16 g_ql[(size_t)Md * Hd];
static __device__ __nv_bfloat16 g_kh[(size_t)Md * Hd];
static __device__ __nv_bfloat16 g_kl[(size_t)Md * Hd];
static __device__ __nv_bfloat16 g_vth[(size_t)Md * Hd];
static __device__ __nv_bfloat16 g_vtl[(size_t)Md * Hd];

// ---------------------------------------------------------------------------
// Helpers
// ---------------------------------------------------------------------------
__device__ __forceinline__ uint32_t smem_to_u32(const void* p) {
    uint32_t a;
    asm("{ .reg .u64 t; cvta.to.shared.u64 t, %1; cvt.u32.u64 %0, t; }" : "=r"(a) : "l"(p));
    return a;
}
#define LDSM4(r, addr) \
    asm volatile("ldmatrix.sync.aligned.m8n8.x4.shared.b16 {%0,%1,%2,%3}, [%4];" \
        : "=r"((r)[0]), "=r"((r)[1]), "=r"((r)[2]), "=r"((r)[3]) : "r"(addr))
#define MMA16816(c, a, b) \
    asm volatile("mma.sync.aligned.m16n8k16.row.col.f32.bf16.bf16.f32 " \
        "{%0,%1,%2,%3}, {%4,%5,%6,%7}, {%8,%9}, {%0,%1,%2,%3};" \
        : "+f"((c)[0]), "+f"((c)[1]), "+f"((c)[2]), "+f"((c)[3]) \
        : "r"((a)[0]), "r"((a)[1]), "r"((a)[2]), "r"((a)[3]), "r"((b)[0]), "r"((b)[1]))
#define CPA16(saddr, gaddr) \
    asm volatile("cp.async.cg.shared.global [%0], [%1], 16;" :: "r"(saddr), "l"(gaddr))

// pack bf16x2: lo -> low half, hi -> high half
__device__ __forceinline__ uint32_t packbf2(float lo, float hi) {
    uint32_t d;
    asm("cvt.rn.bf16x2.f32 %0, %1, %2;" : "=r"(d) : "f"(hi), "f"(lo));
    return d;
}

// ---------------------------------------------------------------------------
// RoPE trig table (double precision)
// ---------------------------------------------------------------------------
__global__ void build_trig(const int* __restrict__ pos) {
    int i = blockIdx.x * blockDim.x + threadIdx.x;
    if (i >= Md * 64) return;
    int d = i & 63;
    int m = i >> 6;
    double a = (double)pos[m] * exp(-(double)d * 0.1439115683121279);
    g_cos[i] = (float)cos(a);
    g_sin[i] = (float)sin(a);
}

// ---------------------------------------------------------------------------
// fp32 -> bf16 hi/lo split (GEMM inputs)
// ---------------------------------------------------------------------------
__global__ void split_kernel(const float* __restrict__ src,
                             __nv_bfloat16* __restrict__ hi,
                             __nv_bfloat16* __restrict__ lo, int n4) {
    int i = blockIdx.x * blockDim.x + threadIdx.x;
    if (i >= n4) return;
    float4 v = ((const float4*)src)[i];
    __nv_bfloat16 h0 = __float2bfloat16(v.x);
    __nv_bfloat16 h1 = __float2bfloat16(v.y);
    __nv_bfloat16 h2 = __float2bfloat16(v.z);
    __nv_bfloat16 h3 = __float2bfloat16(v.w);
    __nv_bfloat16 l0 = __float2bfloat16(v.x - __bfloat162float(h0));
    __nv_bfloat16 l1 = __float2bfloat16(v.y - __bfloat162float(h1));
    __nv_bfloat16 l2 = __float2bfloat16(v.z - __bfloat162float(h2));
    __nv_bfloat16 l3 = __float2bfloat16(v.w - __bfloat162float(h3));
    ((__nv_bfloat162*)hi)[i * 2]     = __nv_bfloat162(h0, h1);
    ((__nv_bfloat162*)hi)[i * 2 + 1] = __nv_bfloat162(h2, h3);
    ((__nv_bfloat162*)lo)[i * 2]     = __nv_bfloat162(l0, l1);
    ((__nv_bfloat162*)lo)[i * 2 + 1] = __nv_bfloat162(l2, l3);
}

// ---------------------------------------------------------------------------
// RoPE + split + repack Q,K:  g_qkv -> q_hi/lo, k_hi/lo  in [b,h,s,d]
// Q pre-scaled by 1/sqrt(HD).
// ---------------------------------------------------------------------------
__global__ void qk_rope_split() {
    int i = blockIdx.x * blockDim.x + threadIdx.x;
    if (i >= Md * NHd * 64) return;
    int d = i & 63;
    int h = (i >> 6) & (NHd - 1);
    int m = i >> 11;
    int b = m >> 11, s = m & (Sd - 1);
    float c  = g_cos[(m << 6) + d];
    float sn = g_sin[(m << 6) + d];
    const float* q = g_qkv + (size_t)m * QKVN + (size_t)h * HDd;
    const float* k = q + Hd;
    const float scale = 0.08838834764831845f;

    float q1 = q[d], q2 = q[d + 64];
    float qa = (q1 * c - q2 * sn) * scale;
    float qb = (q2 * c + q1 * sn) * scale;
    float k1 = k[d], k2 = k[d + 64];
    float ka = k1 * c - k2 * sn;
    float kb = k2 * c + k1 * sn;

    size_t o = ((size_t)(b * NHd + h) * Sd + s) * HDd + d;
    __nv_bfloat16 qah = __float2bfloat16(qa), qbh = __float2bfloat16(qb);
    __nv_bfloat16 kah = __float2bfloat16(ka), kbh = __float2bfloat16(kb);
    g_qh[o] = qah;       g_qh[o + 64] = qbh;
    g_ql[o] = __float2bfloat16(qa - __bfloat162float(qah));
    g_ql[o + 64] = __float2bfloat16(qb - __bfloat162float(qbh));
    g_kh[o] = kah;       g_kh[o + 64] = kbh;
    g_kl[o] = __float2bfloat16(ka - __bfloat162float(kah));
    g_kl[o + 64] = __float2bfloat16(kb - __bfloat162float(kbh));
}

// ---------------------------------------------------------------------------
// V transpose + split:  g_qkv V -> vt_hi/lo [b,h,d,s]
// grid (bh, S/32, HD/32), block (32,8), 32x32 smem tile
// ---------------------------------------------------------------------------
__global__ void v_trans_split() {
    __shared__ float tile[32][33];
    int bh = blockIdx.x;
    int so = blockIdx.y * 32;
    int dz = blockIdx.z * 32;
    int b = bh >> 5, h = bh & 31;
    int tx = threadIdx.x, ty = threadIdx.y;
#pragma unroll
    for (int r = 0; r < 4; r++) {
        int s = so + ty + r * 8;
        tile[ty + r * 8][tx] =
            g_qkv[(size_t)(b * Sd + s) * QKVN + 2 * Hd + h * HDd + dz + tx];
    }
    __syncthreads();
#pragma unroll
    for (int r = 0; r < 4; r++) {
        int d = dz + ty + r * 8;
        float v = tile[tx][ty + r * 8];
        __nv_bfloat16 vh = __float2bfloat16(v);
        size_t o = ((size_t)bh * HDd + d) * Sd + so + tx;
        g_vth[o] = vh;
        g_vtl[o] = __float2bfloat16(v - __bfloat162float(vh));
    }
}

// ---------------------------------------------------------------------------
// bf16x3 GEMM on mma.sync (unchanged from round 3, proven)
// ---------------------------------------------------------------------------
#define BKg      32
#define TSTRIDE  80
#define TILE_B   (128 * TSTRIDE)
#define STAGE_B  (4 * TILE_B)

__device__ __forceinline__ void load_stage(uint32_t sbase, const char* const* tp,
                                           int k0, int tid) {
#pragma unroll
    for (int t = 0; t < 8; t++) {
        int idx = t * 256 + tid;
        int tile = idx >> 9;
        int r = (idx >> 2) & 127;
        int c = idx & 3;
        uint32_t saddr = sbase + tile * TILE_B + r * TSTRIDE + c * 16;
        const char* g = tp[tile] + ((size_t)r * Kdim + k0) * 2 + c * 16;
        CPA16(saddr, g);
    }
    asm volatile("cp.async.commit_group;" ::: "memory");
}

__global__ __launch_bounds__(256, 2) void gemm_tc(
    const __nv_bfloat16* __restrict__ Ahi, const __nv_bfloat16* __restrict__ Alo,
    const __nv_bfloat16* __restrict__ Bhi, const __nv_bfloat16* __restrict__ Blo,
    const float* __restrict__ bias, float* __restrict__ C,
    int Ndim, int n_coltiles)
{
    extern __shared__ __align__(128) char smem[];
    const uint32_t sb = smem_to_u32(smem);
    const int tid = threadIdx.x;
    const int lane = tid & 31, warp = tid >> 5;
    const int wm = warp & 1, wn = warp >> 1;

    int bid = blockIdx.x;
    int tpb = 8 * n_coltiles;
    int band = bid / tpb;
    int rem = bid - band * tpb;
    size_t row0 = (size_t)(band * 8 + (rem & 7)) * 128;
    size_t col0 = (size_t)(rem >> 3) * 128;

    const char* tp[4] = {
        (const char*)(Ahi + row0 * Kdim),
        (const char*)(Alo + row0 * Kdim),
        (const char*)(Bhi + col0 * Kdim),
        (const char*)(Blo + col0 * Kdim) };

    float acc[4][4][4];
#pragma unroll
    for (int mf = 0; mf < 4; mf++)
#pragma unroll
        for (int nf = 0; nf < 4; nf++)
#pragma unroll
            for (int e = 0; e < 4; e++) acc[mf][nf][e] = 0.f;

    load_stage(sb, tp, 0, tid);

    const int NKB = Kdim / BKg;
    for (int kb = 0; kb < NKB; kb++) {
        asm volatile("cp.async.wait_group 0;" ::: "memory");
        __syncthreads();
        if (kb + 1 < NKB)
            load_stage(sb + ((kb + 1) & 1) * STAGE_B, tp, (kb + 1) * BKg, tid);
        const uint32_t cs = sb + (kb & 1) * STAGE_B;

#pragma unroll
        for (int ks = 0; ks < 2; ks++) {
            const uint32_t a_off = cs + (wm * 64 + (lane & 15)) * TSTRIDE
                                 + ((lane >> 4) * 16) + ks * 32;
            const uint32_t b_off = cs + 2 * TILE_B
                                 + (wn * 32 + (lane & 7) + (lane >> 4) * 8) * TSTRIDE
                                 + (((lane >> 3) & 1) * 16) + ks * 32;

            uint32_t ah[4][4], bh[4][2], bt[4][2];
#pragma unroll
            for (int mf = 0; mf < 4; mf++) LDSM4(ah[mf], a_off + mf * 16 * TSTRIDE);
#pragma unroll
            for (int ng = 0; ng < 2; ng++) {
                uint32_t r[4];
                LDSM4(r, b_off + ng * 16 * TSTRIDE);
                bh[ng * 2][0] = r[0]; bh[ng * 2][1] = r[1];
                bh[ng * 2 + 1][0] = r[2]; bh[ng * 2 + 1][1] = r[3];
            }
#pragma unroll
            for (int mf = 0; mf < 4; mf++)
#pragma unroll
                for (int nf = 0; nf < 4; nf++) MMA16816(acc[mf][nf], ah[mf], bh[nf]);

#pragma unroll
            for (int ng = 0; ng < 2; ng++) {
                uint32_t r[4];
                LDSM4(r, b_off + TILE_B + ng * 16 * TSTRIDE);
                bt[ng * 2][0] = r[0]; bt[ng * 2][1] = r[1];
                bt[ng * 2 + 1][0] = r[2]; bt[ng * 2 + 1][1] = r[3];
            }
#pragma unroll
            for (int mf = 0; mf < 4; mf++)
#pragma unroll
                for (int nf = 0; nf < 4; nf++) MMA16816(acc[mf][nf], ah[mf], bt[nf]);

#pragma unroll
            for (int mf = 0; mf < 4; mf++) LDSM4(ah[mf], a_off + TILE_B + mf * 16 * TSTRIDE);
#pragma unroll
            for (int mf = 0; mf < 4; mf++)
#pragma unroll
                for (int nf = 0; nf < 4; nf++) MMA16816(acc[mf][nf], ah[mf], bh[nf]);
        }
    }

#pragma unroll
    for (int mf = 0; mf < 4; mf++) {
        int row = (int)row0 + wm * 64 + mf * 16 + (lane >> 2);
#pragma unroll
        for (int nf = 0; nf < 4; nf++) {
            int col = (int)col0 + wn * 32 + nf * 8 + (lane & 3) * 2;
            float b0 = bias[col], b1 = bias[col + 1];
            float* p0 = C + (size_t)row * Ndim + col;
            *(float2*)p0 = make_float2(acc[mf][nf][0] + b0, acc[mf][nf][1] + b1);
            float* p1 = p0 + 8 * (size_t)Ndim;
            *(float2*)p1 = make_float2(acc[mf][nf][2] + b0, acc[mf][nf][3] + b1);
        }
    }
}

// ---------------------------------------------------------------------------
// Tensor-core causal flash attention (bf16x3 split, FA-2 register pipeline)
// CTA: 128 q-rows x 64-key tiles, 8 warps (warp = 16 q rows), 256 threads.
// Smem: Q hi/lo [128][272B], K hi/lo [64][272B] x2buf, VT hi/lo [128][144B] x2buf
// ---------------------------------------------------------------------------
#define QKST 272
#define VST  144
#define SQ_LO   34816
#define SK_BASE 69632
#define SK_SZ   34816
#define SK_LO   17408
#define SV_BASE 139264
#define SV_SZ   36864
#define SV_LO   18432
#define ATT_SMEM 212992

__global__ __launch_bounds__(256) void attn_tc() {
    extern __shared__ __align__(128) char smem[];
    const uint32_t sb = smem_to_u32(smem);
    const int tid = threadIdx.x;
    const int lane = tid & 31, warp = tid >> 5;

    // heavy q-tiles first
    int bid = blockIdx.x;
    int qt = (Sd / 128 - 1) - (bid >> 6);
    int bh = bid & 63;
    int b = bh >> 5, h = bh & 31;
    const int q0 = qt * 128;

    const __nv_bfloat16* qh_g = g_qh + ((size_t)bh * Sd + q0) * HDd;
    const __nv_bfloat16* ql_g = g_ql + ((size_t)bh * Sd + q0) * HDd;
    const __nv_bfloat16* kh_g = g_kh + (size_t)bh * Sd * HDd;
    const __nv_bfloat16* kl_g = g_kl + (size_t)bh * Sd * HDd;
    const __nv_bfloat16* vth_g = g_vth + (size_t)bh * HDd * Sd;
    const __nv_bfloat16* vtl_g = g_vtl + (size_t)bh * HDd * Sd;

    // ---- load Q (hi+lo) ----
#pragma unroll
    for (int t = 0; t < 8; t++) {
        int idx = t * 256 + tid;
        int r = idx >> 4, c = idx & 15;
        CPA16(sb + r * QKST + c * 16, (const char*)(qh_g + (size_t)r * HDd + c * 8));
        CPA16(sb + SQ_LO + r * QKST + c * 16, (const char*)(ql_g + (size_t)r * HDd + c * 8));
    }
    // ---- load K/V tile 0 ----
    {
        uint32_t sk = sb + SK_BASE, sv = sb + SV_BASE;
#pragma unroll
        for (int t = 0; t < 4; t++) {
            int idx = t * 256 + tid;
            int r = idx >> 4, c = idx & 15;
            CPA16(sk + r * QKST + c * 16, (const char*)(kh_g + (size_t)r * HDd + c * 8));
            CPA16(sk + SK_LO + r * QKST + c * 16, (const char*)(kl_g + (size_t)r * HDd + c * 8));
            int dr = idx >> 3, cc = idx & 7;
            CPA16(sv + dr * VST + cc * 16, (const char*)(vth_g + (size_t)dr * Sd + cc * 8));
            CPA16(sv + SV_LO + dr * VST + cc * 16, (const char*)(vtl_g + (size_t)dr * Sd + cc * 8));
        }
    }
    asm volatile("cp.async.commit_group;" ::: "memory");

    float m0 = NEG_INF, m1 = NEG_INF, l0 = 0.f, l1 = 0.f;
    float o[16][4];
#pragma unroll
    for (int nf = 0; nf < 16; nf++)
#pragma unroll
        for (int e = 0; e < 4; e++) o[nf][e] = 0.f;

    const int r_lo = warp * 16 + (lane >> 2);   // within-tile q row (c0,c1)
    const int nt = (q0 + 128) / 64;

    for (int jt = 0; jt < nt; jt++) {
        const int j0 = jt * 64;
        asm volatile("cp.async.wait_group 0;" ::: "memory");
        __syncthreads();
        // prefetch next tile into other buffer (overlaps compute)
        if (jt + 1 < nt) {
            int jn = (jt + 1) * 64;
            uint32_t sk = sb + SK_BASE + ((jt + 1) & 1) * SK_SZ;
            uint32_t sv = sb + SV_BASE + ((jt + 1) & 1) * SV_SZ;
#pragma unroll
            for (int t = 0; t < 4; t++) {
                int idx = t * 256 + tid;
                int r = idx >> 4, c = idx & 15;
                CPA16(sk + r * QKST + c * 16, (const char*)(kh_g + (size_t)(jn + r) * HDd + c * 8));
                CPA16(sk + SK_LO + r * QKST + c * 16, (const char*)(kl_g + (size_t)(jn + r) * HDd + c * 8));
                int dr = idx >> 3, cc = idx & 7;
                CPA16(sv + dr * VST + cc * 16, (const char*)(vth_g + (size_t)dr * Sd + jn + cc * 8));
                CPA16(sv + SV_LO + dr * VST + cc * 16, (const char*)(vtl_g + (size_t)dr * Sd + jn + cc * 8));
            }
            asm volatile("cp.async.commit_group;" ::: "memory");
        }

        const uint32_t sk = sb + SK_BASE + (jt & 1) * SK_SZ;
        const uint32_t sv = sb + SV_BASE + (jt & 1) * SV_SZ;

        // ---- S = Q K^T (3-way split) ----
        float s[8][4];
#pragma unroll
        for (int nf = 0; nf < 8; nf++)
#pragma unroll
            for (int e = 0; e < 4; e++) s[nf][e] = 0.f;

#pragma unroll
        for (int ks = 0; ks < 8; ks++) {
            const uint32_t a_off = sb + (warp * 16 + (lane & 15)) * QKST
                                 + ((lane >> 4) * 16) + ks * 32;
            const uint32_t b_off = sk + ((lane & 7) + (lane >> 4) * 8) * QKST
                                 + (((lane >> 3) & 1) * 16) + ks * 32;
            uint32_t qhf[4], qlf[4];
            LDSM4(qhf, a_off);
            LDSM4(qlf, a_off + SQ_LO);
#pragma unroll
            for (int ng = 0; ng < 4; ng++) {
                uint32_t kr[4], b01[2], b23[2];
                LDSM4(kr, b_off + ng * 16 * QKST);
                b01[0] = kr[0]; b01[1] = kr[1];
                b23[0] = kr[2]; b23[1] = kr[3];
                MMA16816(s[2 * ng], qhf, b01);
                MMA16816(s[2 * ng + 1], qhf, b23);
                MMA16816(s[2 * ng], qlf, b01);
                MMA16816(s[2 * ng + 1], qlf, b23);
                LDSM4(kr, b_off + SK_LO + ng * 16 * QKST);
                b01[0] = kr[0]; b01[1] = kr[1];
                b23[0] = kr[2]; b23[1] = kr[3];
                MMA16816(s[2 * ng], qhf, b01);
                MMA16816(s[2 * ng + 1], qhf, b23);
            }
        }

        // ---- causal mask (last two tiles only) ----
        if (j0 + 64 > q0) {
            int row0g = q0 + r_lo;
#pragma unroll
            for (int nf = 0; nf < 8; nf++) {
                int colg = j0 + nf * 8 + (lane & 3) * 2;
#pragma unroll
                for (int e = 0; e < 2; e++) {
                    if (colg + e > row0g)     s[nf][e] = NEG_INF;
                    if (colg + e > row0g + 8) s[nf][2 + e] = NEG_INF;
                }
            }
        }

        // ---- online softmax ----
        float mx0 = NEG_INF, mx1 = NEG_INF;
#pragma unroll
        for (int nf = 0; nf < 8; nf++) {
            mx0 = fmaxf(mx0, fmaxf(s[nf][0], s[nf][1]));
            mx1 = fmaxf(mx1, fmaxf(s[nf][2], s[nf][3]));
        }
        mx0 = fmaxf(mx0, __shfl_xor_sync(0xffffffffu, mx0, 1));
        mx0 = fmaxf(mx0, __shfl_xor_sync(0xffffffffu, mx0, 2));
        mx1 = fmaxf(mx1, __shfl_xor_sync(0xffffffffu, mx1, 1));
        mx1 = fmaxf(mx1, __shfl_xor_sync(0xffffffffu, mx1, 2));
        float mn0 = fmaxf(m0, mx0), mn1 = fmaxf(m1, mx1);
        float al0 = __expf(m0 - mn0), al1 = __expf(m1 - mn1);
        m0 = mn0; m1 = mn1;
        float sum0 = 0.f, sum1 = 0.f;
#pragma unroll
        for (int nf = 0; nf < 8; nf++) {
            s[nf][0] = __expf(s[nf][0] - mn0); sum0 += s[nf][0];
            s[nf][1] = __expf(s[nf][1] - mn0); sum0 += s[nf][1];
            s[nf][2] = __expf(s[nf][2] - mn1); sum1 += s[nf][2];
            s[nf][3] = __expf(s[nf][3] - mn1); sum1 += s[nf][3];
        }
        sum0 += __shfl_xor_sync(0xffffffffu, sum0, 1);
        sum0 += __shfl_xor_sync(0xffffffffu, sum0, 2);
        sum1 += __shfl_xor_sync(0xffffffffu, sum1, 1);
        sum1 += __shfl_xor_sync(0xffffffffu, sum1, 2);
        l0 = l0 * al0 + sum0;
        l1 = l1 * al1 + sum1;
#pragma unroll
        for (int nf = 0; nf < 16; nf++) {
            o[nf][0] *= al0; o[nf][1] *= al0;
            o[nf][2] *= al1; o[nf][3] *= al1;
        }

        // ---- P hi/lo fragments in registers ----
        uint32_t phi[4][4], plo[4][4];
#pragma unroll
        for (int kk = 0; kk < 4; kk++) {
#pragma unroll
            for (int half = 0; half < 2; half++) {   // nfrag 2kk, 2kk+1
                const float* sv4 = s[2 * kk + half];
                float h0 = __bfloat162float(__float2bfloat16(sv4[0]));
                float h1 = __bfloat162float(__float2bfloat16(sv4[1]));
                float h2 = __bfloat162float(__float2bfloat16(sv4[2]));
                float h3 = __bfloat162float(__float2bfloat16(sv4[3]));
                phi[kk][2 * half + 0] = packbf2(h0, h1);
                phi[kk][2 * half + 1] = packbf2(h2, h3);
                plo[kk][2 * half + 0] = packbf2(sv4[0] - h0, sv4[1] - h1);
                plo[kk][2 * half + 1] = packbf2(sv4[2] - h2, sv4[3] - h3);
            }
        }
        // reorder: A-frag = {a0 (k0-7 row), a1 (k0-7 row+8), a2 (k8-15 row), a3}
        // built above as [2*half + e]: half0 -> a0,a1 ; half1 -> a2,a3   (ok)

        // ---- O += P V (3-way split) ----
#pragma unroll
        for (int ks = 0; ks < 4; ks++) {
            const uint32_t vb = sv + ((lane & 7) + (lane >> 4) * 8) * VST
                              + (((lane >> 3) & 1) * 16) + ks * 32;
#pragma unroll
            for (int ng = 0; ng < 8; ng++) {
                uint32_t vr[4], b01[2], b23[2];
                LDSM4(vr, vb + ng * 16 * VST);
                b01[0] = vr[0]; b01[1] = vr[1];
                b23[0] = vr[2]; b23[1] = vr[3];
                MMA16816(o[2 * ng], phi[ks], b01);
                MMA16816(o[2 * ng + 1], phi[ks], b23);
                MMA16816(o[2 * ng], plo[ks], b01);
                MMA16816(o[2 * ng + 1], plo[ks], b23);
                LDSM4(vr, vb + SV_LO + ng * 16 * VST);
                b01[0] = vr[0]; b01[1] = vr[1];
                b23[0] = vr[2]; b23[1] = vr[3];
                MMA16816(o[2 * ng], phi[ks], b01);
                MMA16816(o[2 * ng + 1], phi[ks], b23);
            }
        }
    }

    // ---- epilogue: normalize, split to bf16 hi/lo, write ctx ----
    float inv0 = 1.f / l0, inv1 = 1.f / l1;
    int rowg0 = b * Sd + q0 + r_lo;
#pragma unroll
    for (int nf = 0; nf < 16; nf++) {
        int col = h * HDd + nf * 8 + (lane & 3) * 2;
        {
            float v0 = o[nf][0] * inv0, v1 = o[nf][1] * inv0;
            float h0 = __bfloat162float(__float2bfloat16(v0));
            float h1 = __bfloat162float(__float2bfloat16(v1));
            size_t off = ((size_t)rowg0 * Hd + col) >> 1;
            ((uint32_t*)g_ctx_hi)[off] = packbf2(h0, h1);
            ((uint32_t*)g_ctx_lo)[off] = packbf2(v0 - h0, v1 - h1);
        }
        {
            float v0 = o[nf][2] * inv1, v1 = o[nf][3] * inv1;
            float h0 = __bfloat162float(__float2bfloat16(v0));
            float h1 = __bfloat162float(__float2bfloat16(v1));
            size_t off = ((size_t)(rowg0 + 8) * Hd + col) >> 1;
            ((uint32_t*)g_ctx_hi)[off] = packbf2(h0, h1);
            ((uint32_t*)g_ctx_lo)[off] = packbf2(v0 - h0, v1 - h1);
        }
    }
}

// ---------------------------------------------------------------------------
// Launch
// ---------------------------------------------------------------------------
extern "C" void kernel_launch(void* const* d_in, const int* in_sizes, int n_in,
                              void* d_out, int out_size)
{
    const int*   pos   = (const int*)  d_in[0];
    const float* hid   = (const float*)d_in[1];
    const float* w_qkv = (const float*)d_in[2];
    const float* b_qkv = (const float*)d_in[3];
    const float* w_out = (const float*)d_in[4];
    const float* b_out = (const float*)d_in[5];
    float* out = (float*)d_out;
    (void)in_sizes; (void)n_in; (void)out_size;

    const size_t gemm_smem = 2 * STAGE_B;
    cudaFuncSetAttribute(gemm_tc, cudaFuncAttributeMaxDynamicSharedMemorySize, (int)gemm_smem);
    cudaFuncSetAttribute(attn_tc, cudaFuncAttributeMaxDynamicSharedMemorySize, ATT_SMEM);

    float* qkv_ptr = nullptr;
    __nv_bfloat16 *hid_hi, *hid_lo, *wqkv_hi, *wqkv_lo, *wout_hi, *wout_lo, *ctx_hi, *ctx_lo;
    cudaGetSymbolAddress((void**)&qkv_ptr, g_qkv);
    cudaGetSymbolAddress((void**)&hid_hi,  g_hid_hi);
    cudaGetSymbolAddress((void**)&hid_lo,  g_hid_lo);
    cudaGetSymbolAddress((void**)&wqkv_hi, g_wqkv_hi);
    cudaGetSymbolAddress((void**)&wqkv_lo, g_wqkv_lo);
    cudaGetSymbolAddress((void**)&wout_hi, g_wout_hi);
    cudaGetSymbolAddress((void**)&wout_lo, g_wout_lo);
    cudaGetSymbolAddress((void**)&ctx_hi,  g_ctx_hi);
    cudaGetSymbolAddress((void**)&ctx_lo,  g_ctx_lo);

    build_trig<<<(Md * 64 + 255) / 256, 256>>>(pos);

    int n4_hid  = Md * Hd / 4;
    int n4_wqkv = QKVN * Hd / 4;
    int n4_wout = Hd * Hd / 4;
    split_kernel<<<(n4_hid  + 255) / 256, 256>>>(hid,   hid_hi,  hid_lo,  n4_hid);
    split_kernel<<<(n4_wqkv + 255) / 256, 256>>>(w_qkv, wqkv_hi, wqkv_lo, n4_wqkv);
    split_kernel<<<(n4_wout + 255) / 256, 256>>>(w_out, wout_hi, wout_lo, n4_wout);

    // QKV GEMM: [4096,12288]
    gemm_tc<<<(Md / 128) * (QKVN / 128), 256, gemm_smem>>>(
        hid_hi, hid_lo, wqkv_hi, wqkv_lo, b_qkv, qkv_ptr, QKVN, QKVN / 128);

    // RoPE + split + repack Q,K ; transpose + split V
    qk_rope_split<<<(Md * NHd * 64 + 255) / 256, 256>>>();
    v_trans_split<<<dim3(Bd * NHd, Sd / 32, HDd / 32), dim3(32, 8)>>>();

    // Attention (tensor core)
    attn_tc<<<(Sd / 128) * (Bd * NHd), 256, ATT_SMEM>>>();

    // Out GEMM: [4096,4096]
    gemm_tc<<<(Md / 128) * (Hd / 128), 256, gemm_smem>>>(
        ctx_hi, ctx_lo, wout_hi, wout_lo, b_out, out, Hd, Hd / 128);
}